// round 8
// baseline (speedup 1.0000x reference)
#include <cuda_runtime.h>
#include <math.h>

#define TT 48
#define SS 1024
#define HS 512
#define BB 256
#define NB2 128
#define TAG_START 45
#define TAG_STOP  46

typedef unsigned long long u64;

// scratch (device globals: allocation-free)
__device__ float g_vec[2][BB][64];   // [0]=alpha (fwd), [1]=gamma (bwd)
__device__ int   g_eac[2][BB];
__device__ float g_gold[BB];

// ---- packed f32x2 helpers ----
__device__ __forceinline__ u64 ffma2(u64 a, u64 b, u64 c){
    u64 d; asm("fma.rn.f32x2 %0, %1, %2, %3;" : "=l"(d) : "l"(a), "l"(b), "l"(c)); return d;
}
__device__ __forceinline__ u64 fadd2(u64 a, u64 b){
    u64 d; asm("add.rn.f32x2 %0, %1, %2;" : "=l"(d) : "l"(a), "l"(b)); return d;
}
__device__ __forceinline__ u64 pack2(float lo, float hi){
    u64 d; asm("mov.b64 %0, {%1, %2};" : "=l"(d) : "f"(lo), "f"(hi)); return d;
}
__device__ __forceinline__ void unpack2(u64 v, float& lo, float& hi){
    asm("mov.b64 {%0, %1}, %2;" : "=f"(lo), "=f"(hi) : "l"(v));
}
__device__ __forceinline__ float2 expf2(float2 f){
    return make_float2(__expf(f.x), __expf(f.y));
}
__device__ __forceinline__ float2 ldf2(const float* p, bool act){
    return act ? *(const float2*)p : make_float2(0.f, 0.f);
}

// matvec over one 48-vector in smem + exact pow2 renorm factor from p[0]
__device__ __forceinline__ void step_core(
    const float* rp, const u64* W0, const u64* W1,
    float& s0, float& s1, int& e, float& c)
{
    ulonglong2 P0 = *(const ulonglong2*)&rp[0];
    float p0lo, p0hi; unpack2(P0.x, p0lo, p0hi); (void)p0hi;
    e = ((__float_as_int(p0lo) >> 23) & 0xff) - 127;
    e = max(-60, min(60, e));
    c = __int_as_float((127 - e) << 23);
    u64 A0=0ull, A1=0ull, C0=0ull, C1=0ull;
    #pragma unroll
    for (int q = 0; q < 12; q++){
        ulonglong2 P = (q == 0) ? P0 : *(const ulonglong2*)&rp[4*q];
        A0 = ffma2(W0[2*q],   P.x, A0);
        A1 = ffma2(W1[2*q],   P.x, A1);
        C0 = ffma2(W0[2*q+1], P.y, C0);
        C1 = ffma2(W1[2*q+1], P.y, C1);
    }
    u64 S0 = fadd2(A0, C0), S1 = fadd2(A1, C1);
    float l0, h0, l1, h1; unpack2(S0, l0, h0); unpack2(S1, l1, h1);
    s0 = l0 + h0; s1 = l1 + h1;
}

// forward: p_new = (W p)*E*c ; masked -> p_old*c ; returns value to store
__device__ __forceinline__ float2 fstep_one(
    const float (*pshseq)[64], int pb, const u64* W0, const u64* W1,
    float2 ev, float m, float2& vmy, int& eacc)
{
    float s0, s1; int e; float c;
    step_core(pshseq[pb], W0, W1, s0, s1, e, c);
    float qx = s0 * (ev.x * c);
    float qy = s1 * (ev.y * c);
    vmy.x = (m > 0.5f) ? qx : vmy.x * c;
    vmy.y = (m > 0.5f) ? qy : vmy.y * c;
    eacc += e;
    return vmy;
}

// backward: g_new = (W^T h)*c ; masked -> g_old*c ; store g_new * E_next
__device__ __forceinline__ float2 bstep_one(
    const float (*pshseq)[64], int pb, const u64* W0, const u64* W1,
    float2 en, float m, float2& vmy, int& eacc)
{
    float s0, s1; int e; float c;
    step_core(pshseq[pb], W0, W1, s0, s1, e, c);
    float qx = s0 * c, qy = s1 * c;
    vmy.x = (m > 0.5f) ? qx : vmy.x * c;
    vmy.y = (m > 0.5f) ? qy : vmy.y * c;
    eacc += e;
    return make_float2(vmy.x * en.x, vmy.y * en.y);
}

#define FPAIR(EA, MA, EB, MB) do {                                            \
    float2 oa = fstep_one(psh[0], pb, W0, W1, (EA), (MA), vmy0, eacc0);       \
    float2 ob = fstep_one(psh[1], pb, W0, W1, (EB), (MB), vmy1, eacc1);       \
    if (act){ *(float2*)&psh[0][pb^1][j0] = oa;                               \
              *(float2*)&psh[1][pb^1][j0] = ob; }                             \
    pb ^= 1; __syncwarp();                                                    \
} while(0)

#define BPAIR(EA, MA, EB, MB) do {                                            \
    float2 oa = bstep_one(psh[0], pb, W0, W1, (EA), (MA), vmy0, eacc0);       \
    float2 ob = bstep_one(psh[1], pb, W0, W1, (EB), (MB), vmy1, eacc1);       \
    if (act){ *(float2*)&psh[0][pb^1][j0] = oa;                               \
              *(float2*)&psh[1][pb^1][j0] = ob; }                             \
    pb ^= 1; __syncwarp();                                                    \
} while(0)

__global__ void __launch_bounds__(32) crf_scan_kernel(
    const float* __restrict__ feats,
    const float* __restrict__ masks,
    const void*  __restrict__ tagsp,
    const float* __restrict__ trans)
{
    const int lane = threadIdx.x;
    const int b0   = 2*blockIdx.x, b1 = b0 + 1;
    const int dir  = blockIdx.y;
    const int j0   = 2*lane;
    const bool act = (lane < 24);
    const float* fA = feats + (size_t)b0 * SS * TT;
    const float* fBp = feats + (size_t)b1 * SS * TT;
    const float* mA = masks + (size_t)b0 * SS;
    const float* mBq = masks + (size_t)b1 * SS;

    // ---------------- gold-score blocks (two batches, sequential) ----------
    if (dir == 2){
        const int* t32 = (const int*)tagsp;
        int det = t32[1]|t32[3]|t32[5]|t32[7]|t32[9]|t32[11]|t32[13]|t32[15];
        const bool is64 = (det == 0);
        const long long* t64 = (const long long*)tagsp;

        #pragma unroll
        for (int s = 0; s < 2; s++){
            const int bb = b0 + s;
            const float* fb = (s == 0) ? fA : fBp;
            const float* mb = (s == 0) ? mA : mBq;
            float g = 0.f, lenf = 0.f;
            for (int si = lane; si < SS; si += 32){
                float m = mb[si];
                long long base = (long long)bb * SS + si;
                int tg = is64 ? (int)t64[base] : t32[base];
                int pv = (si == 0) ? TAG_START : (is64 ? (int)t64[base-1] : t32[base-1]);
                g    += (fb[si*TT + tg] + trans[tg*TT + pv]) * m;
                lenf += m;
            }
            #pragma unroll
            for (int o = 16; o; o >>= 1){
                g    += __shfl_xor_sync(0xffffffffu, g,    o);
                lenf += __shfl_xor_sync(0xffffffffu, lenf, o);
            }
            if (lane == 0){
                int len = (int)lenf;
                int last = (len == 0) ? TAG_START
                                      : (is64 ? (int)t64[(long long)bb*SS + len - 1]
                                              : t32[(long long)bb*SS + len - 1]);
                g_gold[bb] = g + trans[TAG_STOP*TT + last];
            }
        }
        return;
    }

    // ---------------- scan blocks: two interleaved sequences ---------------
    __shared__ __align__(16) float psh[2][2][64];   // [seq][buf][vec]

    // fwd: lane holds rows j0,j1 of exp(trans). bwd: rows of exp(trans)^T.
    u64 W0[24], W1[24];
    #pragma unroll
    for (int kk = 0; kk < 24; kk++){
        float a0=0.f, a1=0.f, c0=0.f, c1=0.f;
        if (act){
            if (dir == 0){
                float2 t0 = *(const float2*)&trans[j0*TT + 2*kk];
                float2 t1 = *(const float2*)&trans[(j0+1)*TT + 2*kk];
                a0 = __expf(t0.x); a1 = __expf(t0.y);
                c0 = __expf(t1.x); c1 = __expf(t1.y);
            } else {
                a0 = __expf(trans[(2*kk  )*TT + j0]);
                a1 = __expf(trans[(2*kk+1)*TT + j0]);
                c0 = __expf(trans[(2*kk  )*TT + j0+1]);
                c1 = __expf(trans[(2*kk+1)*TT + j0+1]);
            }
        }
        W0[kk] = pack2(a0, a1);
        W1[kk] = pack2(c0, c1);
    }

    float2 vmy0, vmy1;
    int eacc0 = 0, eacc1 = 0, pb = 0;
    if (dir == 0){
        vmy0.x = (j0   == TAG_START) ? 1.f : 0.f;
        vmy0.y = (j0+1 == TAG_START) ? 1.f : 0.f;
        vmy1 = vmy0;
        if (act){
            *(float2*)&psh[0][0][j0] = vmy0;
            *(float2*)&psh[1][0][j0] = vmy1;
        }
    } else {
        float w0 = act ? __expf(trans[TAG_STOP*TT + j0  ]) : 0.f;
        float w1 = act ? __expf(trans[TAG_STOP*TT + j0+1]) : 0.f;
        vmy0 = make_float2(w0, w1);
        vmy1 = vmy0;
        float2 eLa = expf2(ldf2(&fA [(size_t)1023*TT + j0], act));
        float2 eLb = expf2(ldf2(&fBp[(size_t)1023*TT + j0], act));
        if (act){
            *(float2*)&psh[0][0][j0] = make_float2(w0*eLa.x, w1*eLa.y);
            *(float2*)&psh[1][0][j0] = make_float2(w0*eLb.x, w1*eLb.y);
        }
    }
    __syncwarp();

    if (dir == 0){
        float2 eA0[4], eA1[4], eB0[4], eB1[4];
        float4 mA0, mA1, mB0, mB1;
        #pragma unroll
        for (int u = 0; u < 4; u++){
            eA0[u] = expf2(ldf2(&fA [(size_t)u*TT + j0], act));
            eB0[u] = expf2(ldf2(&fBp[(size_t)u*TT + j0], act));
        }
        mA0 = *(const float4*)&mA[0];
        mB0 = *(const float4*)&mBq[0];

        for (int sb = 0; sb < HS; sb += 8){
            #pragma unroll
            for (int u = 0; u < 4; u++){
                eA1[u] = expf2(ldf2(&fA [(size_t)(sb+4+u)*TT + j0], act));
                eB1[u] = expf2(ldf2(&fBp[(size_t)(sb+4+u)*TT + j0], act));
            }
            mA1 = *(const float4*)&mA[sb+4];
            mB1 = *(const float4*)&mBq[sb+4];

            FPAIR(eA0[0], mA0.x, eB0[0], mB0.x);
            FPAIR(eA0[1], mA0.y, eB0[1], mB0.y);
            FPAIR(eA0[2], mA0.z, eB0[2], mB0.z);
            FPAIR(eA0[3], mA0.w, eB0[3], mB0.w);

            if (sb + 8 < HS){
                #pragma unroll
                for (int u = 0; u < 4; u++){
                    eA0[u] = expf2(ldf2(&fA [(size_t)(sb+8+u)*TT + j0], act));
                    eB0[u] = expf2(ldf2(&fBp[(size_t)(sb+8+u)*TT + j0], act));
                }
                mA0 = *(const float4*)&mA[sb+8];
                mB0 = *(const float4*)&mBq[sb+8];
            }

            FPAIR(eA1[0], mA1.x, eB1[0], mB1.x);
            FPAIR(eA1[1], mA1.y, eB1[1], mB1.y);
            FPAIR(eA1[2], mA1.z, eB1[2], mB1.z);
            FPAIR(eA1[3], mA1.w, eB1[3], mB1.w);
        }
    } else {
        // iteration i: consumes mask[1023-i]; stores E[1022-i] into next psh
        float2 eA0[4], eA1[4], eB0[4], eB1[4];
        float4 mA0, mA1, mB0, mB1;
        #pragma unroll
        for (int u = 0; u < 4; u++){
            eA0[u] = expf2(ldf2(&fA [(size_t)(1022-u)*TT + j0], act));
            eB0[u] = expf2(ldf2(&fBp[(size_t)(1022-u)*TT + j0], act));
        }
        mA0 = *(const float4*)&mA[1020];    // reversed: m[u] = comp[3-u]
        mB0 = *(const float4*)&mBq[1020];

        for (int sb = 0; sb < HS; sb += 8){
            #pragma unroll
            for (int u = 0; u < 4; u++){
                eA1[u] = expf2(ldf2(&fA [(size_t)(1022-(sb+4+u))*TT + j0], act));
                eB1[u] = expf2(ldf2(&fBp[(size_t)(1022-(sb+4+u))*TT + j0], act));
            }
            mA1 = *(const float4*)&mA[1020 - (sb+4)];
            mB1 = *(const float4*)&mBq[1020 - (sb+4)];

            BPAIR(eA0[0], mA0.w, eB0[0], mB0.w);
            BPAIR(eA0[1], mA0.z, eB0[1], mB0.z);
            BPAIR(eA0[2], mA0.y, eB0[2], mB0.y);
            BPAIR(eA0[3], mA0.x, eB0[3], mB0.x);

            if (sb + 8 < HS){
                #pragma unroll
                for (int u = 0; u < 4; u++){
                    eA0[u] = expf2(ldf2(&fA [(size_t)(1022-(sb+8+u))*TT + j0], act));
                    eB0[u] = expf2(ldf2(&fBp[(size_t)(1022-(sb+8+u))*TT + j0], act));
                }
                mA0 = *(const float4*)&mA[1020 - (sb+8)];
                mB0 = *(const float4*)&mBq[1020 - (sb+8)];
            }

            BPAIR(eA1[0], mA1.w, eB1[0], mB1.w);
            BPAIR(eA1[1], mA1.z, eB1[1], mB1.z);
            BPAIR(eA1[2], mA1.y, eB1[2], mB1.y);
            BPAIR(eA1[3], mA1.x, eB1[3], mB1.x);
        }
    }

    if (act){
        *(float2*)&g_vec[dir][b0][j0] = vmy0;
        *(float2*)&g_vec[dir][b1][j0] = vmy1;
    } else {
        g_vec[dir][b0][2*lane] = 0.f; g_vec[dir][b0][2*lane+1] = 0.f;
        g_vec[dir][b1][2*lane] = 0.f; g_vec[dir][b1][2*lane+1] = 0.f;
    }
    if (lane == 0){ g_eac[dir][b0] = eacc0; g_eac[dir][b1] = eacc1; }
}

__global__ void __launch_bounds__(32) crf_combine_kernel(float* __restrict__ out)
{
    const int lane = threadIdx.x;
    const int b    = blockIdx.x;
    float dot = 0.f;
    if (lane < 24){
        float2 a = *(const float2*)&g_vec[0][b][2*lane];
        float2 g = *(const float2*)&g_vec[1][b][2*lane];
        dot = a.x*g.x + a.y*g.y;
    }
    #pragma unroll
    for (int o = 16; o; o >>= 1) dot += __shfl_xor_sync(0xffffffffu, dot, o);
    if (lane == 0){
        double logz = (double)(g_eac[0][b] + g_eac[1][b]) * M_LN2
                    + (double)__logf(dot);
        out[b] = (float)(logz - (double)g_gold[b]);
    }
}

extern "C" void kernel_launch(void* const* d_in, const int* in_sizes, int n_in,
                              void* d_out, int out_size)
{
    const float* feats = (const float*)d_in[0];
    const float* masks = (const float*)d_in[1];
    const void*  tags  = (const void*) d_in[2];
    const float* trans = (const float*)d_in[3];
    float* out = (float*)d_out;
    dim3 grid(NB2, 3);
    crf_scan_kernel<<<grid, 32>>>(feats, masks, tags, trans);
    crf_combine_kernel<<<BB, 32>>>(out);
}

// round 10
// speedup vs baseline: 2.2195x; 2.2195x over previous
#include <cuda_runtime.h>
#include <math.h>

#define TT 48
#define SS 1024
#define HS 512
#define BB 256
#define TAG_START 45
#define TAG_STOP  46

typedef unsigned long long u64;

// scratch (device globals: allocation-free)
__device__ float g_vec[2][BB][64];   // [0]=alpha (fwd), [1]=gamma (bwd)
__device__ int   g_eac[2][BB];
__device__ float g_gold[BB];

// ---- packed f32x2 helpers ----
__device__ __forceinline__ u64 ffma2(u64 a, u64 b, u64 c){
    u64 d; asm("fma.rn.f32x2 %0, %1, %2, %3;" : "=l"(d) : "l"(a), "l"(b), "l"(c)); return d;
}
__device__ __forceinline__ u64 fadd2(u64 a, u64 b){
    u64 d; asm("add.rn.f32x2 %0, %1, %2;" : "=l"(d) : "l"(a), "l"(b)); return d;
}
__device__ __forceinline__ u64 pack2(float lo, float hi){
    u64 d; asm("mov.b64 %0, {%1, %2};" : "=l"(d) : "f"(lo), "f"(hi)); return d;
}
__device__ __forceinline__ void unpack2(u64 v, float& lo, float& hi){
    asm("mov.b64 {%0, %1}, %2;" : "=f"(lo), "=f"(hi) : "l"(v));
}
__device__ __forceinline__ float2 expf2(float2 f){
    return make_float2(__expf(f.x), __expf(f.y));
}
__device__ __forceinline__ float2 ldf2(const float* p, bool act){
    return act ? *(const float2*)p : make_float2(0.f, 0.f);
}

// matvec over smem vector; produces s0,s1 and P0 (first 16B, reused for renorm)
#define MATVEC                                                                \
    const float* rp = &psh[pb][0];                                            \
    ulonglong2 P0 = *(const ulonglong2*)&rp[0];                               \
    u64 A0=0ull, A1=0ull, C0=0ull, C1=0ull;                                   \
    _Pragma("unroll")                                                         \
    for (int q = 0; q < 12; q++){                                             \
        ulonglong2 P = (q == 0) ? P0 : *(const ulonglong2*)&rp[4*q];          \
        A0 = ffma2(W0[2*q],   P.x, A0);                                       \
        A1 = ffma2(W1[2*q],   P.x, A1);                                       \
        C0 = ffma2(W0[2*q+1], P.y, C0);                                       \
        C1 = ffma2(W1[2*q+1], P.y, C1);                                       \
    }                                                                         \
    u64 S0 = fadd2(A0, C0), S1 = fadd2(A1, C1);                               \
    float l0, h0, l1, h1; unpack2(S0, l0, h0); unpack2(S1, l1, h1);           \
    float s0 = l0 + h0, s1 = l1 + h1;

// exact pow2 renorm factor from p[0] (exponent only, integer-exact)
#define RENORM                                                                \
    float p0lo, p0hi; unpack2(P0.x, p0lo, p0hi); (void)p0hi;                  \
    int e = ((__float_as_int(p0lo) >> 23) & 0xff) - 127;                      \
    e = max(-60, min(60, e));                                                 \
    float c = __int_as_float((127 - e) << 23);                                \
    eacc += e;

// forward steps: renormed / plain
#define FSTEP_R(EV, M) do { MATVEC RENORM                                     \
    float qx = s0 * ((EV).x * c), qy = s1 * ((EV).y * c);                     \
    vmy.x = ((M) > 0.5f) ? qx : vmy.x * c;                                    \
    vmy.y = ((M) > 0.5f) ? qy : vmy.y * c;                                    \
    if (act) *(float2*)&psh[pb ^ 1][j0] = vmy;                                \
    pb ^= 1; __syncwarp();                                                    \
} while(0)

#define FSTEP_P(EV, M) do { MATVEC                                            \
    float qx = s0 * (EV).x, qy = s1 * (EV).y;                                 \
    vmy.x = ((M) > 0.5f) ? qx : vmy.x;                                        \
    vmy.y = ((M) > 0.5f) ? qy : vmy.y;                                        \
    if (act) *(float2*)&psh[pb ^ 1][j0] = vmy;                                \
    pb ^= 1; __syncwarp();                                                    \
} while(0)

// backward steps: renormed / plain (store g*E_next for the following step)
#define BSTEP_R(EN, M) do { MATVEC RENORM                                     \
    float qx = s0 * c, qy = s1 * c;                                           \
    vmy.x = ((M) > 0.5f) ? qx : vmy.x * c;                                    \
    vmy.y = ((M) > 0.5f) ? qy : vmy.y * c;                                    \
    if (act) *(float2*)&psh[pb ^ 1][j0] = make_float2(vmy.x*(EN).x, vmy.y*(EN).y); \
    pb ^= 1; __syncwarp();                                                    \
} while(0)

#define BSTEP_P(EN, M) do { MATVEC                                            \
    vmy.x = ((M) > 0.5f) ? s0 : vmy.x;                                        \
    vmy.y = ((M) > 0.5f) ? s1 : vmy.y;                                        \
    if (act) *(float2*)&psh[pb ^ 1][j0] = make_float2(vmy.x*(EN).x, vmy.y*(EN).y); \
    pb ^= 1; __syncwarp();                                                    \
} while(0)

__global__ void __launch_bounds__(32) crf_scan_kernel(
    const float* __restrict__ feats,
    const float* __restrict__ masks,
    const void*  __restrict__ tagsp,
    const float* __restrict__ trans)
{
    const int lane = threadIdx.x;
    const int b    = blockIdx.x;
    const int dir  = blockIdx.y;
    const int j0   = 2*lane;
    const bool act = (lane < 24);
    const float* fB = feats + (size_t)b * SS * TT;
    const float* mB = masks + (size_t)b * SS;

    // ---------------- gold-score blocks ----------------
    if (dir == 2){
        const int* t32 = (const int*)tagsp;
        int det = t32[1]|t32[3]|t32[5]|t32[7]|t32[9]|t32[11]|t32[13]|t32[15];
        const bool is64 = (det == 0);
        const long long* t64 = (const long long*)tagsp;

        float g = 0.f, lenf = 0.f;
        for (int si = lane; si < SS; si += 32){
            float m = mB[si];
            long long base = (long long)b * SS + si;
            int tg = is64 ? (int)t64[base] : t32[base];
            int pv = (si == 0) ? TAG_START : (is64 ? (int)t64[base-1] : t32[base-1]);
            g    += (fB[si*TT + tg] + trans[tg*TT + pv]) * m;
            lenf += m;
        }
        #pragma unroll
        for (int o = 16; o; o >>= 1){
            g    += __shfl_xor_sync(0xffffffffu, g,    o);
            lenf += __shfl_xor_sync(0xffffffffu, lenf, o);
        }
        if (lane == 0){
            int len = (int)lenf;
            int last = (len == 0) ? TAG_START
                                  : (is64 ? (int)t64[(long long)b*SS + len - 1]
                                          : t32[(long long)b*SS + len - 1]);
            g_gold[b] = g + trans[TAG_STOP*TT + last];
        }
        return;
    }

    // ---------------- scan blocks (dir 0 = fwd, 1 = bwd) ----------------
    __shared__ __align__(16) float psh[2][64];

    u64 W0[24], W1[24];
    #pragma unroll
    for (int kk = 0; kk < 24; kk++){
        float a0=0.f, a1=0.f, c0=0.f, c1=0.f;
        if (act){
            if (dir == 0){
                float2 t0 = *(const float2*)&trans[j0*TT + 2*kk];
                float2 t1 = *(const float2*)&trans[(j0+1)*TT + 2*kk];
                a0 = __expf(t0.x); a1 = __expf(t0.y);
                c0 = __expf(t1.x); c1 = __expf(t1.y);
            } else {
                a0 = __expf(trans[(2*kk  )*TT + j0]);
                a1 = __expf(trans[(2*kk+1)*TT + j0]);
                c0 = __expf(trans[(2*kk  )*TT + j0+1]);
                c1 = __expf(trans[(2*kk+1)*TT + j0+1]);
            }
        }
        W0[kk] = pack2(a0, a1);
        W1[kk] = pack2(c0, c1);
    }

    float2 vmy;
    int eacc = 0, pb = 0;
    if (dir == 0){
        vmy.x = (j0   == TAG_START) ? 1.f : 0.f;
        vmy.y = (j0+1 == TAG_START) ? 1.f : 0.f;
        if (act) *(float2*)&psh[0][j0] = vmy;
    } else {
        float w0 = act ? __expf(trans[TAG_STOP*TT + j0  ]) : 0.f;
        float w1 = act ? __expf(trans[TAG_STOP*TT + j0+1]) : 0.f;
        vmy = make_float2(w0, w1);
        float2 eL = expf2(ldf2(&fB[(size_t)1023*TT + j0], act));
        if (act) *(float2*)&psh[0][j0] = make_float2(w0*eL.x, w1*eL.y);
    }
    __syncwarp();

    // pipeline: raw loads 8 steps ahead, exp computed 4 steps ahead
    float2 e0[4], e1x[4], r1[4], r2[4];
    float4 m0, m1;

    if (dir == 0){
        #pragma unroll
        for (int u = 0; u < 4; u++){
            e0[u] = expf2(ldf2(&fB[(size_t)u*TT + j0], act));
            r1[u] = ldf2(&fB[(size_t)(4+u)*TT + j0], act);
        }
        m0 = *(const float4*)&mB[0];
        m1 = *(const float4*)&mB[4];

        for (int sb = 0; sb < HS; sb += 8){
            // group A: steps sb..sb+3
            float4 m2 = *(const float4*)&mB[sb+8];
            #pragma unroll
            for (int u = 0; u < 4; u++){
                r2[u]  = ldf2(&fB[(size_t)(sb+8+u)*TT + j0], act);
                e1x[u] = expf2(r1[u]);
            }
            FSTEP_R(e0[0], m0.x); FSTEP_P(e0[1], m0.y);
            FSTEP_R(e0[2], m0.z); FSTEP_P(e0[3], m0.w);
            m0 = m2;

            // group B: steps sb+4..sb+7
            float4 m1o = m1;
            m1 = *(const float4*)&mB[sb+12];
            #pragma unroll
            for (int u = 0; u < 4; u++){
                r1[u] = ldf2(&fB[(size_t)(sb+12+u)*TT + j0], act);
                e0[u] = expf2(r2[u]);
            }
            FSTEP_R(e1x[0], m1o.x); FSTEP_P(e1x[1], m1o.y);
            FSTEP_R(e1x[2], m1o.z); FSTEP_P(e1x[3], m1o.w);
        }
    } else {
        // iteration s consumes mask[1023-s]; e-buffer holds exp(f[1022-s])
        #pragma unroll
        for (int u = 0; u < 4; u++){
            e0[u] = expf2(ldf2(&fB[(size_t)(1022-u)*TT + j0], act));
            r1[u] = ldf2(&fB[(size_t)(1022-(4+u))*TT + j0], act);
        }
        m0 = *(const float4*)&mB[1020];   // reversed components
        m1 = *(const float4*)&mB[1016];

        for (int sb = 0; sb < HS; sb += 8){
            float4 m2 = *(const float4*)&mB[1020 - (sb+8)];
            #pragma unroll
            for (int u = 0; u < 4; u++){
                r2[u]  = ldf2(&fB[(size_t)(1022-(sb+8+u))*TT + j0], act);
                e1x[u] = expf2(r1[u]);
            }
            BSTEP_R(e0[0], m0.w); BSTEP_P(e0[1], m0.z);
            BSTEP_R(e0[2], m0.y); BSTEP_P(e0[3], m0.x);
            m0 = m2;

            float4 m1o = m1;
            m1 = *(const float4*)&mB[1020 - (sb+12)];
            #pragma unroll
            for (int u = 0; u < 4; u++){
                r1[u] = ldf2(&fB[(size_t)(1022-(sb+12+u))*TT + j0], act);
                e0[u] = expf2(r2[u]);
            }
            BSTEP_R(e1x[0], m1o.w); BSTEP_P(e1x[1], m1o.z);
            BSTEP_R(e1x[2], m1o.y); BSTEP_P(e1x[3], m1o.x);
        }
    }

    if (act){
        *(float2*)&g_vec[dir][b][j0] = vmy;
    } else {
        g_vec[dir][b][2*lane] = 0.f; g_vec[dir][b][2*lane+1] = 0.f;
    }
    if (lane == 0) g_eac[dir][b] = eacc;
}

__global__ void __launch_bounds__(32) crf_combine_kernel(float* __restrict__ out)
{
    const int lane = threadIdx.x;
    const int b    = blockIdx.x;
    float dot = 0.f;
    if (lane < 24){
        float2 a = *(const float2*)&g_vec[0][b][2*lane];
        float2 g = *(const float2*)&g_vec[1][b][2*lane];
        dot = a.x*g.x + a.y*g.y;
    }
    #pragma unroll
    for (int o = 16; o; o >>= 1) dot += __shfl_xor_sync(0xffffffffu, dot, o);
    if (lane == 0){
        double logz = (double)(g_eac[0][b] + g_eac[1][b]) * M_LN2
                    + (double)__logf(dot);
        out[b] = (float)(logz - (double)g_gold[b]);
    }
}

extern "C" void kernel_launch(void* const* d_in, const int* in_sizes, int n_in,
                              void* d_out, int out_size)
{
    const float* feats = (const float*)d_in[0];
    const float* masks = (const float*)d_in[1];
    const void*  tags  = (const void*) d_in[2];
    const float* trans = (const float*)d_in[3];
    float* out = (float*)d_out;
    dim3 grid(BB, 3);
    crf_scan_kernel<<<grid, 32>>>(feats, masks, tags, trans);
    crf_combine_kernel<<<BB, 32>>>(out);
}

// round 11
// speedup vs baseline: 2.3842x; 1.0742x over previous
#include <cuda_runtime.h>
#include <math.h>

#define TT 48
#define SS 1024
#define HS 512
#define BB 256
#define TAG_START 45
#define TAG_STOP  46

typedef unsigned long long u64;

// scratch (device globals: allocation-free; zero-initialized at load)
__device__ float    g_vec[2][BB][64];   // [0]=alpha (fwd), [1]=gamma (bwd)
__device__ int      g_eac[2][BB];
__device__ float    g_gold[BB];
__device__ unsigned g_cnt[BB];          // last-finisher counters (reset after use)

// ---- packed f32x2 helpers ----
__device__ __forceinline__ u64 ffma2(u64 a, u64 b, u64 c){
    u64 d; asm("fma.rn.f32x2 %0, %1, %2, %3;" : "=l"(d) : "l"(a), "l"(b), "l"(c)); return d;
}
__device__ __forceinline__ u64 fadd2(u64 a, u64 b){
    u64 d; asm("add.rn.f32x2 %0, %1, %2;" : "=l"(d) : "l"(a), "l"(b)); return d;
}
__device__ __forceinline__ u64 pack2(float lo, float hi){
    u64 d; asm("mov.b64 %0, {%1, %2};" : "=l"(d) : "f"(lo), "f"(hi)); return d;
}
__device__ __forceinline__ void unpack2(u64 v, float& lo, float& hi){
    asm("mov.b64 {%0, %1}, %2;" : "=f"(lo), "=f"(hi) : "l"(v));
}
__device__ __forceinline__ float2 expf2(float2 f){
    return make_float2(__expf(f.x), __expf(f.y));
}
__device__ __forceinline__ float2 ldf2(const float* p, bool act){
    return act ? *(const float2*)p : make_float2(0.f, 0.f);
}

// matvec over smem vector; produces s0,s1 and P0 (first 16B, reused for renorm)
#define MATVEC                                                                \
    const float* rp = &psh[pb][0];                                            \
    ulonglong2 P0 = *(const ulonglong2*)&rp[0];                               \
    u64 A0=0ull, A1=0ull, C0=0ull, C1=0ull;                                   \
    _Pragma("unroll")                                                         \
    for (int q = 0; q < 12; q++){                                             \
        ulonglong2 P = (q == 0) ? P0 : *(const ulonglong2*)&rp[4*q];          \
        A0 = ffma2(W0[2*q],   P.x, A0);                                       \
        A1 = ffma2(W1[2*q],   P.x, A1);                                       \
        C0 = ffma2(W0[2*q+1], P.y, C0);                                       \
        C1 = ffma2(W1[2*q+1], P.y, C1);                                       \
    }                                                                         \
    u64 S0 = fadd2(A0, C0), S1 = fadd2(A1, C1);                               \
    float l0, h0, l1, h1; unpack2(S0, l0, h0); unpack2(S1, l1, h1);           \
    float s0 = l0 + h0, s1 = l1 + h1;

// exact pow2 renorm factor from p[0] (exponent only, integer-exact)
#define RENORM                                                                \
    float p0lo, p0hi; unpack2(P0.x, p0lo, p0hi); (void)p0hi;                  \
    int e = ((__float_as_int(p0lo) >> 23) & 0xff) - 127;                      \
    e = max(-60, min(60, e));                                                 \
    float c = __int_as_float((127 - e) << 23);                                \
    eacc += e;

// forward steps: renormed / plain (pad lanes write zeros into psh[48..63])
#define FSTEP_R(EV, M) do { MATVEC RENORM                                     \
    float qx = s0 * ((EV).x * c), qy = s1 * ((EV).y * c);                     \
    vmy.x = ((M) > 0.5f) ? qx : vmy.x * c;                                    \
    vmy.y = ((M) > 0.5f) ? qy : vmy.y * c;                                    \
    *(float2*)&psh[pb ^ 1][j0] = vmy;                                         \
    pb ^= 1; __syncwarp();                                                    \
} while(0)

#define FSTEP_P(EV, M) do { MATVEC                                            \
    float qx = s0 * (EV).x, qy = s1 * (EV).y;                                 \
    vmy.x = ((M) > 0.5f) ? qx : vmy.x;                                        \
    vmy.y = ((M) > 0.5f) ? qy : vmy.y;                                        \
    *(float2*)&psh[pb ^ 1][j0] = vmy;                                         \
    pb ^= 1; __syncwarp();                                                    \
} while(0)

// backward steps: renormed / plain (store g*E_next for the following step)
#define BSTEP_R(EN, M) do { MATVEC RENORM                                     \
    float qx = s0 * c, qy = s1 * c;                                           \
    vmy.x = ((M) > 0.5f) ? qx : vmy.x * c;                                    \
    vmy.y = ((M) > 0.5f) ? qy : vmy.y * c;                                    \
    *(float2*)&psh[pb ^ 1][j0] = make_float2(vmy.x*(EN).x, vmy.y*(EN).y);     \
    pb ^= 1; __syncwarp();                                                    \
} while(0)

#define BSTEP_P(EN, M) do { MATVEC                                            \
    vmy.x = ((M) > 0.5f) ? s0 : vmy.x;                                        \
    vmy.y = ((M) > 0.5f) ? s1 : vmy.y;                                        \
    *(float2*)&psh[pb ^ 1][j0] = make_float2(vmy.x*(EN).x, vmy.y*(EN).y);     \
    pb ^= 1; __syncwarp();                                                    \
} while(0)

__global__ void __launch_bounds__(32) crf_scan_kernel(
    const float* __restrict__ feats,
    const float* __restrict__ masks,
    const void*  __restrict__ tagsp,
    const float* __restrict__ trans,
    float*       __restrict__ out)
{
    const int lane = threadIdx.x;
    const int b    = blockIdx.x;
    const int dir  = blockIdx.y;
    const int j0   = 2*lane;
    const bool act = (lane < 24);
    const float* fB = feats + (size_t)b * SS * TT;
    const float* mB = masks + (size_t)b * SS;

    if (dir == 2){
        // ---------------- gold-score block ----------------
        const int* t32 = (const int*)tagsp;
        int det = t32[1]|t32[3]|t32[5]|t32[7]|t32[9]|t32[11]|t32[13]|t32[15];
        const bool is64 = (det == 0);
        const long long* t64 = (const long long*)tagsp;

        float g = 0.f, lenf = 0.f;
        for (int si = lane; si < SS; si += 32){
            float m = mB[si];
            long long base = (long long)b * SS + si;
            int tg = is64 ? (int)t64[base] : t32[base];
            int pv = (si == 0) ? TAG_START : (is64 ? (int)t64[base-1] : t32[base-1]);
            g    += (fB[si*TT + tg] + trans[tg*TT + pv]) * m;
            lenf += m;
        }
        #pragma unroll
        for (int o = 16; o; o >>= 1){
            g    += __shfl_xor_sync(0xffffffffu, g,    o);
            lenf += __shfl_xor_sync(0xffffffffu, lenf, o);
        }
        if (lane == 0){
            int len = (int)lenf;
            int last = (len == 0) ? TAG_START
                                  : (is64 ? (int)t64[(long long)b*SS + len - 1]
                                          : t32[(long long)b*SS + len - 1]);
            g_gold[b] = g + trans[TAG_STOP*TT + last];
        }
    } else {
        // ---------------- scan block (dir 0 = fwd, 1 = bwd) ----------------
        __shared__ __align__(16) float psh[2][64];

        u64 W0[24], W1[24];
        #pragma unroll
        for (int kk = 0; kk < 24; kk++){
            float a0=0.f, a1=0.f, c0=0.f, c1=0.f;
            if (act){
                if (dir == 0){
                    float2 t0 = *(const float2*)&trans[j0*TT + 2*kk];
                    float2 t1 = *(const float2*)&trans[(j0+1)*TT + 2*kk];
                    a0 = __expf(t0.x); a1 = __expf(t0.y);
                    c0 = __expf(t1.x); c1 = __expf(t1.y);
                } else {
                    a0 = __expf(trans[(2*kk  )*TT + j0]);
                    a1 = __expf(trans[(2*kk+1)*TT + j0]);
                    c0 = __expf(trans[(2*kk  )*TT + j0+1]);
                    c1 = __expf(trans[(2*kk+1)*TT + j0+1]);
                }
            }
            W0[kk] = pack2(a0, a1);
            W1[kk] = pack2(c0, c1);
        }

        float2 vmy;
        int eacc = 0, pb = 0;
        if (dir == 0){
            vmy.x = (j0   == TAG_START) ? 1.f : 0.f;
            vmy.y = (j0+1 == TAG_START) ? 1.f : 0.f;
            *(float2*)&psh[0][j0] = vmy;
        } else {
            float w0 = act ? __expf(trans[TAG_STOP*TT + j0  ]) : 0.f;
            float w1 = act ? __expf(trans[TAG_STOP*TT + j0+1]) : 0.f;
            vmy = make_float2(w0, w1);
            float2 eL = expf2(ldf2(&fB[(size_t)1023*TT + j0], act));
            *(float2*)&psh[0][j0] = make_float2(w0*eL.x, w1*eL.y);
        }
        __syncwarp();

        // pipeline: raw loads 8 steps ahead, exp computed 4 steps ahead
        float2 e0[4], e1x[4], r1[4], r2[4];
        float4 m0, m1;

        if (dir == 0){
            #pragma unroll
            for (int u = 0; u < 4; u++){
                e0[u] = expf2(ldf2(&fB[(size_t)u*TT + j0], act));
                r1[u] = ldf2(&fB[(size_t)(4+u)*TT + j0], act);
            }
            m0 = *(const float4*)&mB[0];
            m1 = *(const float4*)&mB[4];

            for (int sb = 0; sb < HS; sb += 8){
                float4 m2 = *(const float4*)&mB[sb+8];
                #pragma unroll
                for (int u = 0; u < 4; u++){
                    r2[u]  = ldf2(&fB[(size_t)(sb+8+u)*TT + j0], act);
                    e1x[u] = expf2(r1[u]);
                }
                FSTEP_R(e0[0], m0.x); FSTEP_P(e0[1], m0.y);
                FSTEP_R(e0[2], m0.z); FSTEP_P(e0[3], m0.w);
                m0 = m2;

                float4 m1o = m1;
                m1 = *(const float4*)&mB[sb+12];
                #pragma unroll
                for (int u = 0; u < 4; u++){
                    r1[u] = ldf2(&fB[(size_t)(sb+12+u)*TT + j0], act);
                    e0[u] = expf2(r2[u]);
                }
                FSTEP_R(e1x[0], m1o.x); FSTEP_P(e1x[1], m1o.y);
                FSTEP_R(e1x[2], m1o.z); FSTEP_P(e1x[3], m1o.w);
            }
        } else {
            #pragma unroll
            for (int u = 0; u < 4; u++){
                e0[u] = expf2(ldf2(&fB[(size_t)(1022-u)*TT + j0], act));
                r1[u] = ldf2(&fB[(size_t)(1022-(4+u))*TT + j0], act);
            }
            m0 = *(const float4*)&mB[1020];   // reversed components
            m1 = *(const float4*)&mB[1016];

            for (int sb = 0; sb < HS; sb += 8){
                float4 m2 = *(const float4*)&mB[1020 - (sb+8)];
                #pragma unroll
                for (int u = 0; u < 4; u++){
                    r2[u]  = ldf2(&fB[(size_t)(1022-(sb+8+u))*TT + j0], act);
                    e1x[u] = expf2(r1[u]);
                }
                BSTEP_R(e0[0], m0.w); BSTEP_P(e0[1], m0.z);
                BSTEP_R(e0[2], m0.y); BSTEP_P(e0[3], m0.x);
                m0 = m2;

                float4 m1o = m1;
                m1 = *(const float4*)&mB[1020 - (sb+12)];
                #pragma unroll
                for (int u = 0; u < 4; u++){
                    r1[u] = ldf2(&fB[(size_t)(1022-(sb+12+u))*TT + j0], act);
                    e0[u] = expf2(r2[u]);
                }
                BSTEP_R(e1x[0], m1o.w); BSTEP_P(e1x[1], m1o.z);
                BSTEP_R(e1x[2], m1o.y); BSTEP_P(e1x[3], m1o.x);
            }
        }

        if (act){
            *(float2*)&g_vec[dir][b][j0] = vmy;
        } else {
            g_vec[dir][b][2*lane] = 0.f; g_vec[dir][b][2*lane+1] = 0.f;
        }
        if (lane == 0) g_eac[dir][b] = eacc;
    }

    // -------- last-finisher combine: 3rd block for batch b writes out[b] ----
    __threadfence();
    unsigned old = 0;
    if (lane == 0) old = atomicAdd(&g_cnt[b], 1u);
    old = __shfl_sync(0xffffffffu, old, 0);
    if (old == 2u){
        __threadfence();   // acquire: other blocks' writes now visible
        float dot = 0.f;
        if (lane < 24){
            float2 a = *(const float2*)&g_vec[0][b][2*lane];
            float2 g = *(const float2*)&g_vec[1][b][2*lane];
            dot = a.x*g.x + a.y*g.y;
        }
        #pragma unroll
        for (int o = 16; o; o >>= 1) dot += __shfl_xor_sync(0xffffffffu, dot, o);
        if (lane == 0){
            double logz = (double)(g_eac[0][b] + g_eac[1][b]) * M_LN2
                        + (double)__logf(dot);
            out[b] = (float)(logz - (double)g_gold[b]);
            g_cnt[b] = 0;   // reset for next graph replay
        }
    }
}

extern "C" void kernel_launch(void* const* d_in, const int* in_sizes, int n_in,
                              void* d_out, int out_size)
{
    const float* feats = (const float*)d_in[0];
    const float* masks = (const float*)d_in[1];
    const void*  tags  = (const void*) d_in[2];
    const float* trans = (const float*)d_in[3];
    float* out = (float*)d_out;
    dim3 grid(BB, 3);
    crf_scan_kernel<<<grid, 32>>>(feats, masks, tags, trans, out);
}